// round 16
// baseline (speedup 1.0000x reference)
#include <cuda_runtime.h>
#include <cuda_bf16.h>
#include <cuda_fp16.h>
#include <cstdint>

#define MAXN 40000
#define NPADROWS (MAXN + 64)
#define MAXE 640000
#define INF 128

// ---------------- device scratch ----------------
__device__ uint32_t g_Pb[MAXN * 64];    // x @ W1l   as fp16 pairs (u32 = 2 half)
__device__ float g_Z[MAXN * 128];       // x @ W1r + b1 (f32)
__device__ uint32_t g_P2b[MAXN * 32];   // h @ W2l   as fp16 pairs
__device__ float g_Z2[MAXN * 64];       // h @ W2r + b2 (f32)
__device__ int g_cnt[MAXN];             // zero at load; re-zeroed by k_scan3 each run
__device__ int g_rowptr[MAXN + 1];
__device__ int g_fill[MAXN];
__device__ int g_src[MAXE];
__device__ int g_dst[MAXE];
__device__ int g_col[MAXE];
__device__ int g_part[64];
// x in MMA A-fragment layout: uint4{a0,a1,a2,a3} per (tile16, ks, lane)
#define XTILES (MAXN / 16 + 4)
__device__ uint4 g_xf_hi[XTILES * 8 * 32];
__device__ uint4 g_xf_lo[XTILES * 8 * 32];
// h row-major bf16 pairs (u32 = 2 bf16), 64 pairs/row
__device__ uint32_t g_h_hi[NPADROWS * 64];
__device__ uint32_t g_h_lo[NPADROWS * 64];
// weights in MMA B-fragment layout, hi+lo combined:
// uint4{hi_b0, hi_b1, lo_b0, lo_b1} per (ntile8, ks, lane)
__device__ uint4 g_Wf1[32 * 8 * 32];
__device__ uint4 g_Wf2[16 * 8 * 32];

// ---------------- helpers ----------------
__device__ __forceinline__ uint32_t bfpack(__nv_bfloat16 a, __nv_bfloat16 b) {
    return (uint32_t)__bfloat16_as_ushort(a) | ((uint32_t)__bfloat16_as_ushort(b) << 16);
}
__device__ __forceinline__ void split2(float x, float y, uint32_t& hi, uint32_t& lo) {
    __nv_bfloat16 hx = __float2bfloat16_rn(x), hy = __float2bfloat16_rn(y);
    float rx = x - __bfloat162float(hx), ry = y - __bfloat162float(hy);
    hi = bfpack(hx, hy);
    lo = bfpack(__float2bfloat16_rn(rx), __float2bfloat16_rn(ry));
}
// pack two floats into one u32 of fp16 (first arg in low 16 bits)
__device__ __forceinline__ uint32_t f2h2(float a, float b) {
    __half2 h = __floats2half2_rn(a, b);
    return *(uint32_t*)&h;
}
// unpack u32 fp16-pair -> 2 floats (x = low half)
__device__ __forceinline__ float2 h2f2(uint32_t u) {
    __half2 h = *(__half2*)&u;
    return __half22float2(h);
}
__device__ __forceinline__ void mma_bf16(float* d, const uint32_t* a,
                                         uint32_t b0, uint32_t b1) {
    asm volatile(
        "mma.sync.aligned.m16n8k16.row.col.f32.bf16.bf16.f32 "
        "{%0,%1,%2,%3}, {%4,%5,%6,%7}, {%8,%9}, {%0,%1,%2,%3};"
        : "+f"(d[0]), "+f"(d[1]), "+f"(d[2]), "+f"(d[3])
        : "r"(a[0]), "r"(a[1]), "r"(a[2]), "r"(a[3]), "r"(b0), "r"(b1));
}
__device__ __forceinline__ void wpair(const float* W, int ldw, int nc, int p,
                                      uint32_t& hi, uint32_t& lo) {
    float v0 = W[(2 * p) * ldw + nc];
    float v1 = W[(2 * p + 1) * ldw + nc];
    split2(v0, v1, hi, lo);
}

// ---------------- launch 1: hist + x frag split + weight frag packs ----------------
// Relies on g_cnt == 0 at entry (zero-init at load; re-zeroed by k_scan3 each run).
__global__ void k_prep(const float* __restrict__ x, const void* __restrict__ ei,
                       const float* __restrict__ W1l, const float* __restrict__ W1r,
                       const float* __restrict__ W2l, const float* __restrict__ W2r,
                       int n, int E, int hb, int st) {
    int b = blockIdx.x;
    int tid = threadIdx.x;
    if (b < hb) {  // edge convert + histogram
        int e = b * 256 + tid;
        if (e >= E) return;
        const long long* p64 = (const long long*)ei;
        bool is64 = true;
#pragma unroll
        for (int j = 0; j < 4; j++) {
            unsigned long long v = (unsigned long long)p64[j];
            if (v >> 32) is64 = false;
        }
        int s, d;
        if (is64) {
            s = (int)p64[e];
            d = (int)p64[(size_t)E + e];
        } else {
            const int* p32 = (const int*)ei;
            s = p32[e];
            d = p32[E + e];
        }
        g_src[e] = s;
        g_dst[e] = d;
        atomicAdd(&g_cnt[d], 1);
        return;
    }
    b -= hb;
    if (b < st) {  // x -> A-fragment split: one block per 16-row tile
        int tile = b;
        int s = tid >> 5;
        int lane = tid & 31;
        int g = lane >> 2, q = lane & 3;
        int r0 = tile * 16 + g;
        int r1 = r0 + 8;
        int p0 = s * 8 + q;
        int p2 = p0 + 4;
        float2 f00 = make_float2(0.f, 0.f), f10 = f00, f02 = f00, f12 = f00;
        if (r0 < n) {
            f00 = *(const float2*)(x + (size_t)r0 * 128 + 2 * p0);
            f02 = *(const float2*)(x + (size_t)r0 * 128 + 2 * p2);
        }
        if (r1 < n) {
            f10 = *(const float2*)(x + (size_t)r1 * 128 + 2 * p0);
            f12 = *(const float2*)(x + (size_t)r1 * 128 + 2 * p2);
        }
        uint32_t a0h, a0l, a1h, a1l, a2h, a2l, a3h, a3l;
        split2(f00.x, f00.y, a0h, a0l);
        split2(f10.x, f10.y, a1h, a1l);
        split2(f02.x, f02.y, a2h, a2l);
        split2(f12.x, f12.y, a3h, a3l);
        int idx = (tile * 8 + s) * 32 + lane;
        g_xf_hi[idx] = make_uint4(a0h, a1h, a2h, a3h);
        g_xf_lo[idx] = make_uint4(a0l, a1l, a2l, a3l);
        return;
    }
    b -= st;
    if (b < 32) {  // W1 frag pack: 32 n-tiles (N=256), hi+lo combined uint4
        int idx = b * 256 + tid;            // (t*8+s)*32+lane
        int lane = idx & 31;
        int s = (idx >> 5) & 7;
        int t = idx >> 8;
        int nn = t * 8 + (lane >> 2);
        int q = lane & 3;
        const float* W = (nn < 128) ? W1l : W1r;
        int nc = (nn < 128) ? nn : nn - 128;
        uint32_t h0, l0, h1, l1;
        wpair(W, 128, nc, s * 8 + q, h0, l0);
        wpair(W, 128, nc, s * 8 + q + 4, h1, l1);
        g_Wf1[idx] = make_uint4(h0, h1, l0, l1);
        return;
    }
    b -= 32;
    {  // W2 frag pack: 16 n-tiles (N=128), hi+lo combined uint4
        int idx = b * 256 + tid;
        if (idx >= 16 * 8 * 32) return;
        int lane = idx & 31;
        int s = (idx >> 5) & 7;
        int t = idx >> 8;
        int nn = t * 8 + (lane >> 2);
        int q = lane & 3;
        const float* W = (nn < 64) ? W2l : W2r;
        int nc = (nn < 64) ? nn : nn - 64;
        uint32_t h0, l0, h1, l1;
        wpair(W, 64, nc, s * 8 + q, h0, l0);
        wpair(W, 64, nc, s * 8 + q + 4, h1, l1);
        g_Wf2[idx] = make_uint4(h0, h1, l0, l1);
    }
}

// ---------------- launch 2: block sums ----------------
__global__ void k_scan1(int n) {
    __shared__ int ws[32];
    int i = blockIdx.x * 1024 + threadIdx.x;
    int lane = threadIdx.x & 31, w = threadIdx.x >> 5;
    int v = (i < n) ? g_cnt[i] : 0;
    int s = __reduce_add_sync(0xffffffffu, v);
    if (lane == 0) ws[w] = s;
    __syncthreads();
    if (w == 0) {
        int t = ws[lane];
        t = __reduce_add_sync(0xffffffffu, t);
        if (lane == 0) g_part[blockIdx.x] = t;
    }
}

// ---------------- launch 3: local scan + inline partial-scan + offsets + cnt rezero ----------------
__global__ void k_scan3(int n, int nb) {
    __shared__ int ws[32];
    __shared__ int sbase;
    int b = blockIdx.x;
    int i = b * 1024 + threadIdx.x;
    int lane = threadIdx.x & 31, w = threadIdx.x >> 5;
    int v = (i < n) ? g_cnt[i] : 0;
    if (i < n) g_cnt[i] = 0;  // re-zero for next replay (enables hist-first prep)
    int x = v;
#pragma unroll
    for (int off = 1; off < 32; off <<= 1) {
        int y = __shfl_up_sync(0xffffffffu, x, off);
        if (lane >= off) x += y;
    }
    if (lane == 31) ws[w] = x;
    __syncthreads();
    if (w == 0) {
        int wv = ws[lane];
        int wx = wv;
#pragma unroll
        for (int off = 1; off < 32; off <<= 1) {
            int y = __shfl_up_sync(0xffffffffu, wx, off);
            if (lane >= off) wx += y;
        }
        ws[lane] = wx - wv;
        // inline exclusive scan of the nb block partials (nb <= 64)
        int carry = 0;
        for (int base = 0; base < nb; base += 32) {
            int ii = base + lane;
            int pv = (ii < nb) ? g_part[ii] : 0;
            int px = pv;
#pragma unroll
            for (int off = 1; off < 32; off <<= 1) {
                int y = __shfl_up_sync(0xffffffffu, px, off);
                if (lane >= off) px += y;
            }
            if (ii == b) sbase = carry + px - pv;
            carry += __shfl_sync(0xffffffffu, px, 31);
        }
        if (lane == 0 && b == nb - 1) g_rowptr[n] = carry;
    }
    __syncthreads();
    int excl = x - v + ws[w] + sbase;
    if (i < n) {
        g_rowptr[i] = excl;
        g_fill[i] = excl;
    }
}

// ---------------- launch 4: interleaved CSR fill + GEMM1 (N=256, smem-staged A) ----------------
// GEMM: 256 threads, 8 warps (2M x 4N), CTA tile 64x256. A staged in smem;
// B loaded as one LDG.128 per fragment (hi+lo combined).
__global__ __launch_bounds__(256, 2) void k_mma1_fill(
    const float* __restrict__ bias, uint32_t* __restrict__ outP,
    float* __restrict__ outZ, int n, int fb, int mb, int E, int ilv) {
    __shared__ uint4 sAhi[1024];  // 4 tiles x 8 s x 32 lanes
    __shared__ uint4 sAlo[1024];
    int bx;
    if (ilv) {  // exact 4:1 interleave
        int grp = blockIdx.x / 5, rem = blockIdx.x % 5;
        if (rem < 4) {
            int e = (grp * 4 + rem) * 256 + threadIdx.x;
            if (e < E) {
                int d = g_dst[e];
                int pos = atomicAdd(&g_fill[d], 1);
                g_col[pos] = g_src[e];
            }
            return;
        }
        bx = grp;
    } else {    // fallback: fill first
        if (blockIdx.x < fb) {
            int e = blockIdx.x * 256 + threadIdx.x;
            if (e < E) {
                int d = g_dst[e];
                int pos = atomicAdd(&g_fill[d], 1);
                g_col[pos] = g_src[e];
            }
            return;
        }
        bx = blockIdx.x - fb;
    }
    if (bx >= mb) return;

    int tid = threadIdx.x;
    int wid = tid >> 5, lane = tid & 31;
    int q = lane & 3, g = lane >> 2;
    int warpM = wid >> 2, warpN = wid & 3;
    int rbase = bx * 64 + warpM * 32 + g;

    // prologue: stage this CTA's A fragments (contiguous 16KB hi + 16KB lo)
    {
        int base = bx * 1024;
#pragma unroll
        for (int i = 0; i < 4; i++) {
            int idx = tid + i * 256;
            sAhi[idx] = g_xf_hi[base + idx];
            sAlo[idx] = g_xf_lo[base + idx];
        }
    }
    __syncthreads();

    float acc[2][8][4];
#pragma unroll
    for (int mt = 0; mt < 2; mt++)
#pragma unroll
        for (int nt = 0; nt < 8; nt++)
#pragma unroll
            for (int c = 0; c < 4; c++) acc[mt][nt][c] = 0.0f;

#pragma unroll 2
    for (int s = 0; s < 8; s++) {
        uint4 ah[2], al[2];
#pragma unroll
        for (int mt = 0; mt < 2; mt++) {
            int idx = ((warpM * 2 + mt) * 8 + s) * 32 + lane;
            ah[mt] = sAhi[idx];
            al[mt] = sAlo[idx];
        }
#pragma unroll
        for (int nt = 0; nt < 8; nt++) {
            int idx = ((warpN * 8 + nt) * 8 + s) * 32 + lane;
            uint4 bq = g_Wf1[idx];   // one LDG.128: {hi0, hi1, lo0, lo1}
#pragma unroll
            for (int mt = 0; mt < 2; mt++) {
                mma_bf16(acc[mt][nt], (const uint32_t*)&ah[mt], bq.x, bq.y);
                mma_bf16(acc[mt][nt], (const uint32_t*)&ah[mt], bq.z, bq.w);
                mma_bf16(acc[mt][nt], (const uint32_t*)&al[mt], bq.x, bq.y);
            }
        }
    }

#pragma unroll
    for (int mt = 0; mt < 2; mt++) {
        int r0 = rbase + mt * 16;
        int r1 = r0 + 8;
#pragma unroll
        for (int nt = 0; nt < 8; nt++) {
            int col = warpN * 64 + nt * 8 + q * 2;
            const float* a = acc[mt][nt];
            if (col < 128) {  // P half -> fp16 pair
                if (r0 < n) outP[(size_t)r0 * 64 + (col >> 1)] = f2h2(a[0], a[1]);
                if (r1 < n) outP[(size_t)r1 * 64 + (col >> 1)] = f2h2(a[2], a[3]);
            } else {          // Z half -> f32 + bias
                int c = col - 128;
                float b0 = __ldg(bias + c), b1 = __ldg(bias + c + 1);
                if (r0 < n) *(float2*)(outZ + (size_t)r0 * 128 + c) = make_float2(a[0] + b0, a[1] + b1);
                if (r1 < n) *(float2*)(outZ + (size_t)r1 * 128 + c) = make_float2(a[2] + b0, a[3] + b1);
            }
        }
    }
}

// ---------------- launch 5: h = relu(mean_agg(Pfp16) + Z) -> bf16 split pairs ----------------
__global__ void k_agg_add_128(const uint2* __restrict__ Pb2,
                              const float4* __restrict__ Z4,
                              uint32_t* __restrict__ Hhi,
                              uint32_t* __restrict__ Hlo, int n) {
    int w = (int)((blockIdx.x * (size_t)blockDim.x + threadIdx.x) >> 5);
    int lane = threadIdx.x & 31;
    if (w >= n) return;
    int s = g_rowptr[w], e = g_rowptr[w + 1];
    float a0 = 0.f, a1 = 0.f, a2 = 0.f, a3 = 0.f;
    int j = s;
    for (; j + 8 <= e; j += 8) {
#pragma unroll
        for (int u = 0; u < 8; u++) {
            int c = g_col[j + u];
            uint2 v = Pb2[(size_t)c * 32 + lane];
            float2 f0 = h2f2(v.x), f1 = h2f2(v.y);
            a0 += f0.x; a1 += f0.y; a2 += f1.x; a3 += f1.y;
        }
    }
    for (; j < e; j++) {
        int c = g_col[j];
        uint2 v = Pb2[(size_t)c * 32 + lane];
        float2 f0 = h2f2(v.x), f1 = h2f2(v.y);
        a0 += f0.x; a1 += f0.y; a2 += f1.x; a3 += f1.y;
    }
    int deg = e - s;
    float inv = 1.0f / (float)(deg > 0 ? deg : 1);
    float4 z = Z4[(size_t)w * 32 + lane];
    float r0 = fmaxf(a0 * inv + z.x, 0.f);
    float r1 = fmaxf(a1 * inv + z.y, 0.f);
    float r2 = fmaxf(a2 * inv + z.z, 0.f);
    float r3 = fmaxf(a3 * inv + z.w, 0.f);
    uint32_t h0, l0, h1, l1;
    split2(r0, r1, h0, l0);
    split2(r2, r3, h1, l1);
    ((uint2*)(Hhi + (size_t)w * 64))[lane] = make_uint2(h0, h1);
    ((uint2*)(Hlo + (size_t)w * 64))[lane] = make_uint2(l0, l1);
}

// ---------------- launch 6: GEMM2 (N=128 split 64/64, smem-staged h) ----------------
// h rows staged in smem with row stride 68 u32 (conflict-free banks).
__global__ __launch_bounds__(128, 4) void k_mma2(
    const float* __restrict__ bias, uint32_t* __restrict__ outP,
    float* __restrict__ outZ, int n) {
    __shared__ uint32_t sHhi[64 * 68];
    __shared__ uint32_t sHlo[64 * 68];
    int tid = threadIdx.x;
    int wid = tid >> 5, lane = tid & 31;
    int q = lane & 3, g = lane >> 2;
    int warpM = wid >> 1, warpN = wid & 1;
    int rbase = blockIdx.x * 64 + warpM * 32 + g;

    // prologue: stage 64 rows x 64 u32 of h (hi + lo), MLP=8 per array
    {
        const uint4* ghi = (const uint4*)(g_h_hi + (size_t)blockIdx.x * 64 * 64);
        const uint4* glo = (const uint4*)(g_h_lo + (size_t)blockIdx.x * 64 * 64);
#pragma unroll
        for (int i = 0; i < 8; i++) {
            int idx = tid + i * 128;       // uint4 index, 1024 total
            int row = idx >> 4;            // 16 uint4 per row
            int c4 = idx & 15;
            uint4 vh = ghi[idx];
            uint4 vl = glo[idx];
            *(uint4*)&sHhi[row * 68 + c4 * 4] = vh;
            *(uint4*)&sHlo[row * 68 + c4 * 4] = vl;
        }
    }
    __syncthreads();

    float acc[2][8][4];
#pragma unroll
    for (int mt = 0; mt < 2; mt++)
#pragma unroll
        for (int nt = 0; nt < 8; nt++)
#pragma unroll
            for (int c = 0; c < 4; c++) acc[mt][nt][c] = 0.0f;

    int rl = warpM * 32 + g;  // local row of this thread's group

#pragma unroll 2
    for (int s = 0; s < 8; s++) {
        int kp = s * 8 + q;
        uint32_t Ah[2][4], Al[2][4];
#pragma unroll
        for (int mt = 0; mt < 2; mt++) {
            int r0 = (rl + mt * 16) * 68;
            int r1 = r0 + 8 * 68;
            Ah[mt][0] = sHhi[r0 + kp];
            Ah[mt][1] = sHhi[r1 + kp];
            Ah[mt][2] = sHhi[r0 + kp + 4];
            Ah[mt][3] = sHhi[r1 + kp + 4];
            Al[mt][0] = sHlo[r0 + kp];
            Al[mt][1] = sHlo[r1 + kp];
            Al[mt][2] = sHlo[r0 + kp + 4];
            Al[mt][3] = sHlo[r1 + kp + 4];
        }
#pragma unroll
        for (int nt = 0; nt < 8; nt++) {
            int idx = ((warpN * 8 + nt) * 8 + s) * 32 + lane;
            uint4 bq = g_Wf2[idx];   // one LDG.128: {hi0, hi1, lo0, lo1}
#pragma unroll
            for (int mt = 0; mt < 2; mt++) {
                mma_bf16(acc[mt][nt], Ah[mt], bq.x, bq.y);
                mma_bf16(acc[mt][nt], Ah[mt], bq.z, bq.w);
                mma_bf16(acc[mt][nt], Al[mt], bq.x, bq.y);
            }
        }
    }

#pragma unroll
    for (int mt = 0; mt < 2; mt++) {
        int r0 = rbase + mt * 16;
        int r1 = r0 + 8;
#pragma unroll
        for (int nt = 0; nt < 8; nt++) {
            int col = warpN * 64 + nt * 8 + q * 2;
            const float* a = acc[mt][nt];
            if (col < 64) {   // P2 half -> fp16 pair
                if (r0 < n) outP[(size_t)r0 * 32 + (col >> 1)] = f2h2(a[0], a[1]);
                if (r1 < n) outP[(size_t)r1 * 32 + (col >> 1)] = f2h2(a[2], a[3]);
            } else {          // Z2 half -> f32 + bias
                int c = col - 64;
                float b0 = __ldg(bias + c), b1 = __ldg(bias + c + 1);
                if (r0 < n) *(float2*)(outZ + (size_t)r0 * 64 + c) = make_float2(a[0] + b0, a[1] + b1);
                if (r1 < n) *(float2*)(outZ + (size_t)r1 * 64 + c) = make_float2(a[2] + b0, a[3] + b1);
            }
        }
    }
}

// ---------------- launch 7: out = mean_agg(P2fp16) + Z2 ----------------
__global__ void k_agg_add_64(const uint32_t* __restrict__ Pb,
                             const float2* __restrict__ Z2,
                             float2* __restrict__ out2, int n) {
    int w = (int)((blockIdx.x * (size_t)blockDim.x + threadIdx.x) >> 5);
    int lane = threadIdx.x & 31;
    if (w >= n) return;
    int s = g_rowptr[w], e = g_rowptr[w + 1];
    float a0 = 0.f, a1 = 0.f;
    int j = s;
    for (; j + 8 <= e; j += 8) {
#pragma unroll
        for (int u = 0; u < 8; u++) {
            int c = g_col[j + u];
            float2 f = h2f2(Pb[(size_t)c * 32 + lane]);
            a0 += f.x; a1 += f.y;
        }
    }
    for (; j < e; j++) {
        int c = g_col[j];
        float2 f = h2f2(Pb[(size_t)c * 32 + lane]);
        a0 += f.x; a1 += f.y;
    }
    int deg = e - s;
    float inv = 1.0f / (float)(deg > 0 ? deg : 1);
    float2 z = Z2[(size_t)w * 32 + lane];
    out2[(size_t)w * 32 + lane] = make_float2(a0 * inv + z.x, a1 * inv + z.y);
}

// ---------------- launch ----------------
extern "C" void kernel_launch(void* const* d_in, const int* in_sizes, int n_in,
                              void* d_out, int out_size) {
    const float* x = (const float*)d_in[0];
    const void* edge_index = d_in[1];
    const float* W1l = (const float*)d_in[2];
    const float* b1 = (const float*)d_in[3];
    const float* W1r = (const float*)d_in[4];
    const float* W2l = (const float*)d_in[5];
    const float* b2 = (const float*)d_in[6];
    const float* W2r = (const float*)d_in[7];
    float* out = (float*)d_out;

    int N = in_sizes[0] / INF;
    int E = in_sizes[1] / 2;
    if (N > MAXN) N = MAXN;
    if (E > MAXE) E = MAXE;

    uint32_t *p_Pb, *p_P2b, *hh, *hl;
    float *p_Z, *p_Z2;
    cudaGetSymbolAddress((void**)&p_Pb, g_Pb);
    cudaGetSymbolAddress((void**)&p_Z, g_Z);
    cudaGetSymbolAddress((void**)&p_P2b, g_P2b);
    cudaGetSymbolAddress((void**)&p_Z2, g_Z2);
    cudaGetSymbolAddress((void**)&hh, g_h_hi);
    cudaGetSymbolAddress((void**)&hl, g_h_lo);

    // 1: hist + x frag split + weight packs (g_cnt pre-zeroed by previous run / load)
    int hb = (E + 255) / 256;
    int st = (N + 15) / 16;
    k_prep<<<hb + st + 32 + 16, 256>>>(x, edge_index, W1l, W1r, W2l, W2r, N, E, hb, st);

    // 2-3: scan chain (scan3 folds the partial-scan and re-zeroes g_cnt)
    int nb = (N + 1023) / 1024;
    k_scan1<<<nb, 1024>>>(N);
    k_scan3<<<nb, 1024>>>(N, nb);

    // 4: interleaved CSR fill + layer-1 GEMM (fused N=256), smem-staged A
    int mblocks = (N + 63) / 64;
    int ilv = (hb == 4 * mblocks) ? 1 : 0;
    k_mma1_fill<<<hb + mblocks, 256>>>(b1, p_Pb, p_Z, N, hb, mblocks, E, ilv);

    // 5: h = relu(mean_agg(P) + Z), as bf16 split rows
    k_agg_add_128<<<(N * 32 + 255) / 256, 256>>>(
        (const uint2*)p_Pb, (const float4*)p_Z, hh, hl, N);

    // 6: layer-2 GEMM (N=128 split 64/64), smem-staged h
    k_mma2<<<mblocks, 128>>>(b2, p_P2b, p_Z2, N);

    // 7: final aggregation -> out
    k_agg_add_64<<<(N * 32 + 255) / 256, 256>>>(
        p_P2b, (const float2*)p_Z2, (float2*)out, N);
}

// round 17
// speedup vs baseline: 1.0318x; 1.0318x over previous
#include <cuda_runtime.h>
#include <cuda_bf16.h>
#include <cuda_fp16.h>
#include <cstdint>

#define MAXN 40000
#define NPADROWS (MAXN + 64)
#define MAXE 640000
#define INF 128

// ---------------- device scratch ----------------
__device__ uint32_t g_Pb[MAXN * 64];    // x @ W1l   as fp16 pairs (u32 = 2 half)
__device__ float g_Z[MAXN * 128];       // x @ W1r + b1 (f32)
__device__ uint32_t g_P2b[MAXN * 32];   // h @ W2l   as fp16 pairs
__device__ float g_Z2[MAXN * 64];       // h @ W2r + b2 (f32)
__device__ int g_cnt[MAXN];             // zero at load; re-zeroed by k_scan3 each run
__device__ int g_rowptr[MAXN + 1];
__device__ int g_fill[MAXN];
__device__ int g_src[MAXE];
__device__ int g_dst[MAXE];
__device__ int g_col[MAXE];
__device__ int g_part[64];
// x in MMA A-fragment layout: uint4{a0,a1,a2,a3} per (tile16, ks, lane)
#define XTILES (MAXN / 16 + 4)
__device__ uint4 g_xf_hi[XTILES * 8 * 32];
__device__ uint4 g_xf_lo[XTILES * 8 * 32];
// h row-major bf16 pairs (u32 = 2 bf16), 64 pairs/row
__device__ uint32_t g_h_hi[NPADROWS * 64];
__device__ uint32_t g_h_lo[NPADROWS * 64];
// weights in MMA B-fragment layout, hi+lo combined:
// uint4{hi_b0, hi_b1, lo_b0, lo_b1} per (ntile8, ks, lane)
__device__ uint4 g_Wf1[32 * 8 * 32];
__device__ uint4 g_Wf2[16 * 8 * 32];

// ---------------- helpers ----------------
__device__ __forceinline__ uint32_t bfpack(__nv_bfloat16 a, __nv_bfloat16 b) {
    return (uint32_t)__bfloat16_as_ushort(a) | ((uint32_t)__bfloat16_as_ushort(b) << 16);
}
__device__ __forceinline__ void split2(float x, float y, uint32_t& hi, uint32_t& lo) {
    __nv_bfloat16 hx = __float2bfloat16_rn(x), hy = __float2bfloat16_rn(y);
    float rx = x - __bfloat162float(hx), ry = y - __bfloat162float(hy);
    hi = bfpack(hx, hy);
    lo = bfpack(__float2bfloat16_rn(rx), __float2bfloat16_rn(ry));
}
// pack two floats into one u32 of fp16 (first arg in low 16 bits)
__device__ __forceinline__ uint32_t f2h2(float a, float b) {
    __half2 h = __floats2half2_rn(a, b);
    return *(uint32_t*)&h;
}
// unpack u32 fp16-pair -> 2 floats (x = low half)
__device__ __forceinline__ float2 h2f2(uint32_t u) {
    __half2 h = *(__half2*)&u;
    return __half22float2(h);
}
__device__ __forceinline__ void mma_bf16(float* d, const uint32_t* a,
                                         uint32_t b0, uint32_t b1) {
    asm volatile(
        "mma.sync.aligned.m16n8k16.row.col.f32.bf16.bf16.f32 "
        "{%0,%1,%2,%3}, {%4,%5,%6,%7}, {%8,%9}, {%0,%1,%2,%3};"
        : "+f"(d[0]), "+f"(d[1]), "+f"(d[2]), "+f"(d[3])
        : "r"(a[0]), "r"(a[1]), "r"(a[2]), "r"(a[3]), "r"(b0), "r"(b1));
}
__device__ __forceinline__ void wpair(const float* W, int ldw, int nc, int p,
                                      uint32_t& hi, uint32_t& lo) {
    float v0 = W[(2 * p) * ldw + nc];
    float v1 = W[(2 * p + 1) * ldw + nc];
    split2(v0, v1, hi, lo);
}

// ---------------- launch 1: hist + x frag split + weight frag packs ----------------
// Relies on g_cnt == 0 at entry (zero-init at load; re-zeroed by k_scan3 each run).
__global__ void k_prep(const float* __restrict__ x, const void* __restrict__ ei,
                       const float* __restrict__ W1l, const float* __restrict__ W1r,
                       const float* __restrict__ W2l, const float* __restrict__ W2r,
                       int n, int E, int hb, int st) {
    int b = blockIdx.x;
    int tid = threadIdx.x;
    if (b < hb) {  // edge convert + histogram
        int e = b * 256 + tid;
        if (e >= E) return;
        const long long* p64 = (const long long*)ei;
        bool is64 = true;
#pragma unroll
        for (int j = 0; j < 4; j++) {
            unsigned long long v = (unsigned long long)p64[j];
            if (v >> 32) is64 = false;
        }
        int s, d;
        if (is64) {
            s = (int)p64[e];
            d = (int)p64[(size_t)E + e];
        } else {
            const int* p32 = (const int*)ei;
            s = p32[e];
            d = p32[E + e];
        }
        g_src[e] = s;
        g_dst[e] = d;
        atomicAdd(&g_cnt[d], 1);
        return;
    }
    b -= hb;
    if (b < st) {  // x -> A-fragment split: one block per 16-row tile
        int tile = b;
        int s = tid >> 5;
        int lane = tid & 31;
        int g = lane >> 2, q = lane & 3;
        int r0 = tile * 16 + g;
        int r1 = r0 + 8;
        int p0 = s * 8 + q;
        int p2 = p0 + 4;
        float2 f00 = make_float2(0.f, 0.f), f10 = f00, f02 = f00, f12 = f00;
        if (r0 < n) {
            f00 = *(const float2*)(x + (size_t)r0 * 128 + 2 * p0);
            f02 = *(const float2*)(x + (size_t)r0 * 128 + 2 * p2);
        }
        if (r1 < n) {
            f10 = *(const float2*)(x + (size_t)r1 * 128 + 2 * p0);
            f12 = *(const float2*)(x + (size_t)r1 * 128 + 2 * p2);
        }
        uint32_t a0h, a0l, a1h, a1l, a2h, a2l, a3h, a3l;
        split2(f00.x, f00.y, a0h, a0l);
        split2(f10.x, f10.y, a1h, a1l);
        split2(f02.x, f02.y, a2h, a2l);
        split2(f12.x, f12.y, a3h, a3l);
        int idx = (tile * 8 + s) * 32 + lane;
        g_xf_hi[idx] = make_uint4(a0h, a1h, a2h, a3h);
        g_xf_lo[idx] = make_uint4(a0l, a1l, a2l, a3l);
        return;
    }
    b -= st;
    if (b < 32) {  // W1 frag pack: 32 n-tiles (N=256), hi+lo combined uint4
        int idx = b * 256 + tid;            // (t*8+s)*32+lane
        int lane = idx & 31;
        int s = (idx >> 5) & 7;
        int t = idx >> 8;
        int nn = t * 8 + (lane >> 2);
        int q = lane & 3;
        const float* W = (nn < 128) ? W1l : W1r;
        int nc = (nn < 128) ? nn : nn - 128;
        uint32_t h0, l0, h1, l1;
        wpair(W, 128, nc, s * 8 + q, h0, l0);
        wpair(W, 128, nc, s * 8 + q + 4, h1, l1);
        g_Wf1[idx] = make_uint4(h0, h1, l0, l1);
        return;
    }
    b -= 32;
    {  // W2 frag pack: 16 n-tiles (N=128), hi+lo combined uint4
        int idx = b * 256 + tid;
        if (idx >= 16 * 8 * 32) return;
        int lane = idx & 31;
        int s = (idx >> 5) & 7;
        int t = idx >> 8;
        int nn = t * 8 + (lane >> 2);
        int q = lane & 3;
        const float* W = (nn < 64) ? W2l : W2r;
        int nc = (nn < 64) ? nn : nn - 64;
        uint32_t h0, l0, h1, l1;
        wpair(W, 64, nc, s * 8 + q, h0, l0);
        wpair(W, 64, nc, s * 8 + q + 4, h1, l1);
        g_Wf2[idx] = make_uint4(h0, h1, l0, l1);
    }
}

// ---------------- launch 2: block sums ----------------
__global__ void k_scan1(int n) {
    __shared__ int ws[32];
    int i = blockIdx.x * 1024 + threadIdx.x;
    int lane = threadIdx.x & 31, w = threadIdx.x >> 5;
    int v = (i < n) ? g_cnt[i] : 0;
    int s = __reduce_add_sync(0xffffffffu, v);
    if (lane == 0) ws[w] = s;
    __syncthreads();
    if (w == 0) {
        int t = ws[lane];
        t = __reduce_add_sync(0xffffffffu, t);
        if (lane == 0) g_part[blockIdx.x] = t;
    }
}

// ---------------- launch 3: local scan + inline partial-scan + offsets + cnt rezero ----------------
__global__ void k_scan3(int n, int nb) {
    __shared__ int ws[32];
    __shared__ int sbase;
    int b = blockIdx.x;
    int i = b * 1024 + threadIdx.x;
    int lane = threadIdx.x & 31, w = threadIdx.x >> 5;
    int v = (i < n) ? g_cnt[i] : 0;
    if (i < n) g_cnt[i] = 0;  // re-zero for next replay (enables hist-first prep)
    int x = v;
#pragma unroll
    for (int off = 1; off < 32; off <<= 1) {
        int y = __shfl_up_sync(0xffffffffu, x, off);
        if (lane >= off) x += y;
    }
    if (lane == 31) ws[w] = x;
    __syncthreads();
    if (w == 0) {
        int wv = ws[lane];
        int wx = wv;
#pragma unroll
        for (int off = 1; off < 32; off <<= 1) {
            int y = __shfl_up_sync(0xffffffffu, wx, off);
            if (lane >= off) wx += y;
        }
        ws[lane] = wx - wv;
        // inline exclusive scan of the nb block partials (nb <= 64)
        int carry = 0;
        for (int base = 0; base < nb; base += 32) {
            int ii = base + lane;
            int pv = (ii < nb) ? g_part[ii] : 0;
            int px = pv;
#pragma unroll
            for (int off = 1; off < 32; off <<= 1) {
                int y = __shfl_up_sync(0xffffffffu, px, off);
                if (lane >= off) px += y;
            }
            if (ii == b) sbase = carry + px - pv;
            carry += __shfl_sync(0xffffffffu, px, 31);
        }
        if (lane == 0 && b == nb - 1) g_rowptr[n] = carry;
    }
    __syncthreads();
    int excl = x - v + ws[w] + sbase;
    if (i < n) {
        g_rowptr[i] = excl;
        g_fill[i] = excl;
    }
}

// ---------------- launch 4: interleaved CSR fill + GEMM1 (N-split halves, 3 CTA/SM) ----------------
// GEMM block: 256 threads, 8 warps (2M x 4N), warp tile 32x32, CTA tile 64x128.
// bx = tile*2 + half: half 0 -> P (fp16), half 1 -> Z (f32 + bias).
// A fragments staged in smem (MLP=8 prologue). acc = 32 regs -> 3 CTAs/SM.
__global__ __launch_bounds__(256, 3) void k_mma1_fill(
    const float* __restrict__ bias, uint32_t* __restrict__ outP,
    float* __restrict__ outZ, int n, int fb, int gb, int E, int ilv) {
    __shared__ uint4 sAhi[1024];  // 4 tiles16 x 8 s x 32 lanes
    __shared__ uint4 sAlo[1024];
    int bx;
    if (ilv) {  // exact 2 fill : 1 GEMM interleave (fb == 2*gb)
        int grp = blockIdx.x / 3, rem = blockIdx.x % 3;
        if (rem < 2) {
            int e = (grp * 2 + rem) * 256 + threadIdx.x;
            if (e < E) {
                int d = g_dst[e];
                int pos = atomicAdd(&g_fill[d], 1);
                g_col[pos] = g_src[e];
            }
            return;
        }
        bx = grp;
    } else {    // fallback: fill first
        if (blockIdx.x < fb) {
            int e = blockIdx.x * 256 + threadIdx.x;
            if (e < E) {
                int d = g_dst[e];
                int pos = atomicAdd(&g_fill[d], 1);
                g_col[pos] = g_src[e];
            }
            return;
        }
        bx = blockIdx.x - fb;
    }
    if (bx >= gb) return;

    int tile = bx >> 1;
    int half = bx & 1;
    int tid = threadIdx.x;
    int wid = tid >> 5, lane = tid & 31;
    int q = lane & 3, g = lane >> 2;
    int warpM = wid >> 2, warpN = wid & 3;
    int rbase = tile * 64 + warpM * 32 + g;

    // prologue: stage this tile's A fragments (16KB hi + 16KB lo)
    {
        int base = tile * 1024;
#pragma unroll
        for (int i = 0; i < 4; i++) {
            int idx = tid + i * 256;
            sAhi[idx] = g_xf_hi[base + idx];
            sAlo[idx] = g_xf_lo[base + idx];
        }
    }
    __syncthreads();

    float acc[2][4][4];
#pragma unroll
    for (int mt = 0; mt < 2; mt++)
#pragma unroll
        for (int nt = 0; nt < 4; nt++)
#pragma unroll
            for (int c = 0; c < 4; c++) acc[mt][nt][c] = 0.0f;

    int ntbase = half * 16 + warpN * 4;

#pragma unroll 2
    for (int s = 0; s < 8; s++) {
        uint4 ah[2], al[2];
#pragma unroll
        for (int mt = 0; mt < 2; mt++) {
            int idx = ((warpM * 2 + mt) * 8 + s) * 32 + lane;
            ah[mt] = sAhi[idx];
            al[mt] = sAlo[idx];
        }
#pragma unroll
        for (int nt = 0; nt < 4; nt++) {
            int idx = ((ntbase + nt) * 8 + s) * 32 + lane;
            uint4 bq = g_Wf1[idx];   // {hi0, hi1, lo0, lo1}
#pragma unroll
            for (int mt = 0; mt < 2; mt++) {
                mma_bf16(acc[mt][nt], (const uint32_t*)&ah[mt], bq.x, bq.y);
                mma_bf16(acc[mt][nt], (const uint32_t*)&ah[mt], bq.z, bq.w);
                mma_bf16(acc[mt][nt], (const uint32_t*)&al[mt], bq.x, bq.y);
            }
        }
    }

#pragma unroll
    for (int mt = 0; mt < 2; mt++) {
        int r0 = rbase + mt * 16;
        int r1 = r0 + 8;
#pragma unroll
        for (int nt = 0; nt < 4; nt++) {
            int col = (warpN * 4 + nt) * 8 + q * 2;  // 0..127 within half
            const float* a = acc[mt][nt];
            if (half == 0) {  // P half -> fp16 pair
                if (r0 < n) outP[(size_t)r0 * 64 + (col >> 1)] = f2h2(a[0], a[1]);
                if (r1 < n) outP[(size_t)r1 * 64 + (col >> 1)] = f2h2(a[2], a[3]);
            } else {          // Z half -> f32 + bias
                float b0 = __ldg(bias + col), b1 = __ldg(bias + col + 1);
                if (r0 < n) *(float2*)(outZ + (size_t)r0 * 128 + col) = make_float2(a[0] + b0, a[1] + b1);
                if (r1 < n) *(float2*)(outZ + (size_t)r1 * 128 + col) = make_float2(a[2] + b0, a[3] + b1);
            }
        }
    }
}

// ---------------- launch 5: h = relu(mean_agg(Pfp16) + Z) -> bf16 split pairs ----------------
__global__ void k_agg_add_128(const uint2* __restrict__ Pb2,
                              const float4* __restrict__ Z4,
                              uint32_t* __restrict__ Hhi,
                              uint32_t* __restrict__ Hlo, int n) {
    int w = (int)((blockIdx.x * (size_t)blockDim.x + threadIdx.x) >> 5);
    int lane = threadIdx.x & 31;
    if (w >= n) return;
    int s = g_rowptr[w], e = g_rowptr[w + 1];
    float a0 = 0.f, a1 = 0.f, a2 = 0.f, a3 = 0.f;
    int j = s;
    for (; j + 8 <= e; j += 8) {
#pragma unroll
        for (int u = 0; u < 8; u++) {
            int c = g_col[j + u];
            uint2 v = Pb2[(size_t)c * 32 + lane];
            float2 f0 = h2f2(v.x), f1 = h2f2(v.y);
            a0 += f0.x; a1 += f0.y; a2 += f1.x; a3 += f1.y;
        }
    }
    for (; j < e; j++) {
        int c = g_col[j];
        uint2 v = Pb2[(size_t)c * 32 + lane];
        float2 f0 = h2f2(v.x), f1 = h2f2(v.y);
        a0 += f0.x; a1 += f0.y; a2 += f1.x; a3 += f1.y;
    }
    int deg = e - s;
    float inv = 1.0f / (float)(deg > 0 ? deg : 1);
    float4 z = Z4[(size_t)w * 32 + lane];
    float r0 = fmaxf(a0 * inv + z.x, 0.f);
    float r1 = fmaxf(a1 * inv + z.y, 0.f);
    float r2 = fmaxf(a2 * inv + z.z, 0.f);
    float r3 = fmaxf(a3 * inv + z.w, 0.f);
    uint32_t h0, l0, h1, l1;
    split2(r0, r1, h0, l0);
    split2(r2, r3, h1, l1);
    ((uint2*)(Hhi + (size_t)w * 64))[lane] = make_uint2(h0, h1);
    ((uint2*)(Hlo + (size_t)w * 64))[lane] = make_uint2(l0, l1);
}

// ---------------- launch 6: GEMM2 (N=128 split 64/64, smem-staged h) ----------------
__global__ __launch_bounds__(128, 4) void k_mma2(
    const float* __restrict__ bias, uint32_t* __restrict__ outP,
    float* __restrict__ outZ, int n) {
    __shared__ uint32_t sHhi[64 * 68];
    __shared__ uint32_t sHlo[64 * 68];
    int tid = threadIdx.x;
    int wid = tid >> 5, lane = tid & 31;
    int q = lane & 3, g = lane >> 2;
    int warpM = wid >> 1, warpN = wid & 1;
    int rbase = blockIdx.x * 64 + warpM * 32 + g;

    // prologue: stage 64 rows x 64 u32 of h (hi + lo), MLP=8 per array
    {
        const uint4* ghi = (const uint4*)(g_h_hi + (size_t)blockIdx.x * 64 * 64);
        const uint4* glo = (const uint4*)(g_h_lo + (size_t)blockIdx.x * 64 * 64);
#pragma unroll
        for (int i = 0; i < 8; i++) {
            int idx = tid + i * 128;       // uint4 index, 1024 total
            int row = idx >> 4;            // 16 uint4 per row
            int c4 = idx & 15;
            uint4 vh = ghi[idx];
            uint4 vl = glo[idx];
            *(uint4*)&sHhi[row * 68 + c4 * 4] = vh;
            *(uint4*)&sHlo[row * 68 + c4 * 4] = vl;
        }
    }
    __syncthreads();

    float acc[2][8][4];
#pragma unroll
    for (int mt = 0; mt < 2; mt++)
#pragma unroll
        for (int nt = 0; nt < 8; nt++)
#pragma unroll
            for (int c = 0; c < 4; c++) acc[mt][nt][c] = 0.0f;

    int rl = warpM * 32 + g;  // local row of this thread's group

#pragma unroll 2
    for (int s = 0; s < 8; s++) {
        int kp = s * 8 + q;
        uint32_t Ah[2][4], Al[2][4];
#pragma unroll
        for (int mt = 0; mt < 2; mt++) {
            int r0 = (rl + mt * 16) * 68;
            int r1 = r0 + 8 * 68;
            Ah[mt][0] = sHhi[r0 + kp];
            Ah[mt][1] = sHhi[r1 + kp];
            Ah[mt][2] = sHhi[r0 + kp + 4];
            Ah[mt][3] = sHhi[r1 + kp + 4];
            Al[mt][0] = sHlo[r0 + kp];
            Al[mt][1] = sHlo[r1 + kp];
            Al[mt][2] = sHlo[r0 + kp + 4];
            Al[mt][3] = sHlo[r1 + kp + 4];
        }
#pragma unroll
        for (int nt = 0; nt < 8; nt++) {
            int idx = ((warpN * 8 + nt) * 8 + s) * 32 + lane;
            uint4 bq = g_Wf2[idx];   // {hi0, hi1, lo0, lo1}
#pragma unroll
            for (int mt = 0; mt < 2; mt++) {
                mma_bf16(acc[mt][nt], Ah[mt], bq.x, bq.y);
                mma_bf16(acc[mt][nt], Ah[mt], bq.z, bq.w);
                mma_bf16(acc[mt][nt], Al[mt], bq.x, bq.y);
            }
        }
    }

#pragma unroll
    for (int mt = 0; mt < 2; mt++) {
        int r0 = rbase + mt * 16;
        int r1 = r0 + 8;
#pragma unroll
        for (int nt = 0; nt < 8; nt++) {
            int col = warpN * 64 + nt * 8 + q * 2;
            const float* a = acc[mt][nt];
            if (col < 64) {   // P2 half -> fp16 pair
                if (r0 < n) outP[(size_t)r0 * 32 + (col >> 1)] = f2h2(a[0], a[1]);
                if (r1 < n) outP[(size_t)r1 * 32 + (col >> 1)] = f2h2(a[2], a[3]);
            } else {          // Z2 half -> f32 + bias
                int c = col - 64;
                float b0 = __ldg(bias + c), b1 = __ldg(bias + c + 1);
                if (r0 < n) *(float2*)(outZ + (size_t)r0 * 64 + c) = make_float2(a[0] + b0, a[1] + b1);
                if (r1 < n) *(float2*)(outZ + (size_t)r1 * 64 + c) = make_float2(a[2] + b0, a[3] + b1);
            }
        }
    }
}

// ---------------- launch 7: out = mean_agg(P2fp16) + Z2 ----------------
__global__ void k_agg_add_64(const uint32_t* __restrict__ Pb,
                             const float2* __restrict__ Z2,
                             float2* __restrict__ out2, int n) {
    int w = (int)((blockIdx.x * (size_t)blockDim.x + threadIdx.x) >> 5);
    int lane = threadIdx.x & 31;
    if (w >= n) return;
    int s = g_rowptr[w], e = g_rowptr[w + 1];
    float a0 = 0.f, a1 = 0.f;
    int j = s;
    for (; j + 8 <= e; j += 8) {
#pragma unroll
        for (int u = 0; u < 8; u++) {
            int c = g_col[j + u];
            float2 f = h2f2(Pb[(size_t)c * 32 + lane]);
            a0 += f.x; a1 += f.y;
        }
    }
    for (; j < e; j++) {
        int c = g_col[j];
        float2 f = h2f2(Pb[(size_t)c * 32 + lane]);
        a0 += f.x; a1 += f.y;
    }
    int deg = e - s;
    float inv = 1.0f / (float)(deg > 0 ? deg : 1);
    float2 z = Z2[(size_t)w * 32 + lane];
    out2[(size_t)w * 32 + lane] = make_float2(a0 * inv + z.x, a1 * inv + z.y);
}

// ---------------- launch ----------------
extern "C" void kernel_launch(void* const* d_in, const int* in_sizes, int n_in,
                              void* d_out, int out_size) {
    const float* x = (const float*)d_in[0];
    const void* edge_index = d_in[1];
    const float* W1l = (const float*)d_in[2];
    const float* b1 = (const float*)d_in[3];
    const float* W1r = (const float*)d_in[4];
    const float* W2l = (const float*)d_in[5];
    const float* b2 = (const float*)d_in[6];
    const float* W2r = (const float*)d_in[7];
    float* out = (float*)d_out;

    int N = in_sizes[0] / INF;
    int E = in_sizes[1] / 2;
    if (N > MAXN) N = MAXN;
    if (E > MAXE) E = MAXE;

    uint32_t *p_Pb, *p_P2b, *hh, *hl;
    float *p_Z, *p_Z2;
    cudaGetSymbolAddress((void**)&p_Pb, g_Pb);
    cudaGetSymbolAddress((void**)&p_Z, g_Z);
    cudaGetSymbolAddress((void**)&p_P2b, g_P2b);
    cudaGetSymbolAddress((void**)&p_Z2, g_Z2);
    cudaGetSymbolAddress((void**)&hh, g_h_hi);
    cudaGetSymbolAddress((void**)&hl, g_h_lo);

    // 1: hist + x frag split + weight packs (g_cnt pre-zeroed by previous run / load)
    int hb = (E + 255) / 256;
    int st = (N + 15) / 16;
    k_prep<<<hb + st + 32 + 16, 256>>>(x, edge_index, W1l, W1r, W2l, W2r, N, E, hb, st);

    // 2-3: scan chain (scan3 folds the partial-scan and re-zeroes g_cnt)
    int nb = (N + 1023) / 1024;
    k_scan1<<<nb, 1024>>>(N);
    k_scan3<<<nb, 1024>>>(N, nb);

    // 4: interleaved CSR fill + layer-1 GEMM (N-split halves), 3 CTAs/SM
    int mblocks = (N + 63) / 64;
    int gb = 2 * mblocks;
    int ilv = (hb == 2 * gb) ? 1 : 0;
    k_mma1_fill<<<hb + gb, 256>>>(b1, p_Pb, p_Z, N, hb, gb, E, ilv);

    // 5: h = relu(mean_agg(P) + Z), as bf16 split rows
    k_agg_add_128<<<(N * 32 + 255) / 256, 256>>>(
        (const uint2*)p_Pb, (const float4*)p_Z, hh, hl, N);

    // 6: layer-2 GEMM (N=128 split 64/64), smem-staged h
    k_mma2<<<mblocks, 128>>>(b2, p_P2b, p_Z2, N);

    // 7: final aggregation -> out
    k_agg_add_64<<<(N * 32 + 255) / 256, 256>>>(
        p_P2b, (const float2*)p_Z2, (float2*)out, N);
}